// round 7
// baseline (speedup 1.0000x reference)
#include <cuda_runtime.h>

// Closed-form symmetry constraint:
// Per (batch, class c in {0,1,2}) group of size m with u = x - 0.5:
//   sum_{i<j} (u_i+u_j)^2 = (m-2)*Su2 + Su^2
//   sum_{i<j} (y_i-y_j)^2 = m*Sy2 - Sy^2
//   pairs = m*(m-1)/2
// Output = total / max(count, 1)
//
// MLP-first layout: 128 blocks x 256 threads; each block owns TWO batch rows
// (4 warps per row), each thread owns exactly ONE int4 chunk (4 keypoints) =
// 3 independent 16B loads issued back-to-back with no register pressure.
// All 2048 warps issue their loads immediately -> entire 1.57 MB in flight
// within ~100 cycles, so duration ~ latency + drain instead of serialized
// per-warp latency chains.

__device__ float g_total;
__device__ float g_count;
__device__ unsigned int g_done;

__device__ __forceinline__ void accum(int c, float x, float y,
                                      float (&su)[3], float (&su2)[3],
                                      float (&sy)[3], float (&sy2)[3],
                                      float (&cnt)[3])
{
    const float u = x - 0.5f;
    const float uu = u * u;
    const float yy = y * y;
    #pragma unroll
    for (int k = 0; k < 3; k++) {
        const bool m = (c == k);
        su[k]  += m ? u   : 0.f;
        su2[k] += m ? uu  : 0.f;
        sy[k]  += m ? y   : 0.f;
        sy2[k] += m ? yy  : 0.f;
        cnt[k] += m ? 1.f : 0.f;
    }
}

__global__ void __launch_bounds__(256)
sym_mlp_kernel(const float* __restrict__ kp,   // [B, N, 2]
               const int*   __restrict__ cls,  // [B, N]
               float* __restrict__ out)
{
    const int tid  = threadIdx.x;
    const int wid  = tid >> 5;          // 0..7
    const int lane = tid & 31;
    // Two rows per block; warps 0-3 -> row 0, warps 4-7 -> row 1.
    const int rowInBlk = wid >> 2;
    const int b        = blockIdx.x * 2 + rowInBlk;
    // Chunk within row: 128 int4 chunks (N=512), 4 warps x 32 lanes.
    const int chunk    = ((wid & 3) << 5) | lane;
    const size_t gchunk = (size_t)b * 128 + chunk;

    // Exactly 3 independent wide loads per thread, issued immediately.
    const int4   c4  = reinterpret_cast<const int4*>(cls)[gchunk];
    const float4 p01 = reinterpret_cast<const float4*>(kp)[gchunk * 2];
    const float4 p23 = reinterpret_cast<const float4*>(kp)[gchunk * 2 + 1];

    float su[3]  = {0.f, 0.f, 0.f};
    float su2[3] = {0.f, 0.f, 0.f};
    float sy[3]  = {0.f, 0.f, 0.f};
    float sy2[3] = {0.f, 0.f, 0.f};
    float cnt[3] = {0.f, 0.f, 0.f};

    accum(c4.x, p01.x, p01.y, su, su2, sy, sy2, cnt);
    accum(c4.y, p01.z, p01.w, su, su2, sy, sy2, cnt);
    accum(c4.z, p23.x, p23.y, su, su2, sy, sy2, cnt);
    accum(c4.w, p23.z, p23.w, su, su2, sy, sy2, cnt);

    // Warp butterfly reduction of the 15 register moments.
    #pragma unroll
    for (int off = 16; off > 0; off >>= 1) {
        #pragma unroll
        for (int k = 0; k < 3; k++) {
            su[k]  += __shfl_xor_sync(0xFFFFFFFFu, su[k],  off);
            su2[k] += __shfl_xor_sync(0xFFFFFFFFu, su2[k], off);
            sy[k]  += __shfl_xor_sync(0xFFFFFFFFu, sy[k],  off);
            sy2[k] += __shfl_xor_sync(0xFFFFFFFFu, sy2[k], off);
            cnt[k] += __shfl_xor_sync(0xFFFFFFFFu, cnt[k], off);
        }
    }

    // Per-warp partial moments -> shared; rows stay separate until the
    // closed form (group sums must be complete before squaring).
    __shared__ float s[8][15];
    if (lane == 0) {
        #pragma unroll
        for (int k = 0; k < 3; k++) {
            s[wid][k * 5 + 0] = su[k];
            s[wid][k * 5 + 1] = su2[k];
            s[wid][k * 5 + 2] = sy[k];
            s[wid][k * 5 + 3] = sy2[k];
            s[wid][k * 5 + 4] = cnt[k];
        }
    }
    __syncthreads();

    // Threads 0 and 32 finalize row 0 / row 1 in parallel.
    __shared__ float2 rowRes[2];
    if (lane == 0 && wid < 2) {
        const int base = wid * 4;  // warps [base, base+4) hold this row
        float tot = 0.f, count = 0.f;
        #pragma unroll
        for (int k = 0; k < 3; k++) {
            float Su = 0.f, Su2 = 0.f, Sy = 0.f, Sy2 = 0.f, m = 0.f;
            #pragma unroll
            for (int w = 0; w < 4; w++) {
                Su  += s[base + w][k * 5 + 0];
                Su2 += s[base + w][k * 5 + 1];
                Sy  += s[base + w][k * 5 + 2];
                Sy2 += s[base + w][k * 5 + 3];
                m   += s[base + w][k * 5 + 4];
            }
            tot   += (m - 2.f) * Su2 + Su * Su + m * Sy2 - Sy * Sy;
            count += 0.5f * m * (m - 1.f);
        }
        rowRes[wid] = make_float2(tot, count);
    }
    __syncthreads();

    if (tid == 0) {
        const float tot   = rowRes[0].x + rowRes[1].x;
        const float count = rowRes[0].y + rowRes[1].y;

        atomicAdd(&g_total, tot);
        atomicAdd(&g_count, count);
        __threadfence();
        const unsigned int done = atomicAdd(&g_done, 1u);
        if (done == gridDim.x - 1) {
            // Last block: all prior atomics visible (fenced above).
            const float t = *((volatile float*)&g_total);
            const float c = *((volatile float*)&g_count);
            out[0] = t / fmaxf(c, 1.f);
            // Self-reset so each graph replay starts clean (deterministic).
            *((volatile float*)&g_total) = 0.f;
            *((volatile float*)&g_count) = 0.f;
            __threadfence();
            *((volatile unsigned int*)&g_done) = 0u;
        }
    }
}

extern "C" void kernel_launch(void* const* d_in, const int* in_sizes, int n_in,
                              void* d_out, int out_size)
{
    const float* kp  = (const float*)d_in[0];   // [B, N, 2] float32
    const int*   cls = (const int*)d_in[1];     // [B, N] int32
    float* out = (float*)d_out;

    const int BN = in_sizes[1];   // B * N = 131072
    const int B  = BN / 512;      // 256
    sym_mlp_kernel<<<B / 2, 256>>>(kp, cls, out);
}

// round 8
// speedup vs baseline: 1.2401x; 1.2401x over previous
#include <cuda_runtime.h>

// Closed-form symmetry constraint:
// Per (batch row, class c in {0,1,2}) group of size m with u = x - 0.5:
//   sum_{i<j} (u_i+u_j)^2 = (m-2)*Su2 + Su^2
//   sum_{i<j} (y_i-y_j)^2 = m*Sy2 - Sy^2
//   pairs = m*(m-1)/2
// Output = total / max(count, 1)
//
// 32 blocks x 1024 threads. Each block owns 8 batch rows (4 warps/row);
// each thread owns exactly ONE int4 chunk (4 keypoints): 3 independent 16B
// loads, no register pressure. Class counts come from ballot+popc (uniform
// per warp, no float count reduction); only 12 float moments are butterfly-
// reduced. Short 32-deep global-atomic tail with in-kernel finalize.

__device__ float g_total;
__device__ float g_count;
__device__ unsigned int g_done;

__global__ void __launch_bounds__(1024)
sym_ballot_kernel(const float* __restrict__ kp,   // [B, N, 2]
                  const int*   __restrict__ cls,  // [B, N]
                  float* __restrict__ out)
{
    const int tid  = threadIdx.x;
    const int wid  = tid >> 5;          // 0..31
    const int lane = tid & 31;
    const int rowInBlk = wid >> 2;      // 0..7
    const int b        = blockIdx.x * 8 + rowInBlk;
    const int chunk    = ((wid & 3) << 5) | lane;     // 0..127
    const size_t gchunk = (size_t)b * 128 + chunk;

    // 3 independent wide loads, issued back-to-back.
    const int4   c4  = reinterpret_cast<const int4*>(cls)[gchunk];
    const float4 p01 = reinterpret_cast<const float4*>(kp)[gchunk * 2];
    const float4 p23 = reinterpret_cast<const float4*>(kp)[gchunk * 2 + 1];

    float su[3]  = {0.f, 0.f, 0.f};
    float su2[3] = {0.f, 0.f, 0.f};
    float sy[3]  = {0.f, 0.f, 0.f};
    float sy2[3] = {0.f, 0.f, 0.f};

    // Per-element predicated accumulation (compile-time class indices only).
    {
        const int   cc[4] = {c4.x, c4.y, c4.z, c4.w};
        const float xs[4] = {p01.x, p01.z, p23.x, p23.z};
        const float ys[4] = {p01.y, p01.w, p23.y, p23.w};
        #pragma unroll
        for (int e = 0; e < 4; e++) {
            const float u  = xs[e] - 0.5f;
            const float uu = u * u;
            const float y  = ys[e];
            const float yy = y * y;
            #pragma unroll
            for (int k = 0; k < 3; k++) {
                const bool m = (cc[e] == k);
                su[k]  += m ? u  : 0.f;
                su2[k] += m ? uu : 0.f;
                sy[k]  += m ? y  : 0.f;
                sy2[k] += m ? yy : 0.f;
            }
        }
    }

    // Warp-uniform class counts via ballot+popc (no shuffle reduction needed).
    int cnt[3];
    #pragma unroll
    for (int k = 0; k < 3; k++) {
        cnt[k] = __popc(__ballot_sync(0xFFFFFFFFu, c4.x == k))
               + __popc(__ballot_sync(0xFFFFFFFFu, c4.y == k))
               + __popc(__ballot_sync(0xFFFFFFFFu, c4.z == k))
               + __popc(__ballot_sync(0xFFFFFFFFu, c4.w == k));
    }

    // Butterfly-reduce the 12 float moments across the warp.
    #pragma unroll
    for (int off = 16; off > 0; off >>= 1) {
        #pragma unroll
        for (int k = 0; k < 3; k++) {
            su[k]  += __shfl_xor_sync(0xFFFFFFFFu, su[k],  off);
            su2[k] += __shfl_xor_sync(0xFFFFFFFFu, su2[k], off);
            sy[k]  += __shfl_xor_sync(0xFFFFFFFFu, sy[k],  off);
            sy2[k] += __shfl_xor_sync(0xFFFFFFFFu, sy2[k], off);
        }
    }

    // Per-warp partials: 12 floats + 3 counts (stored as float).
    __shared__ float s[32][16];
    if (lane == 0) {
        #pragma unroll
        for (int k = 0; k < 3; k++) {
            s[wid][k * 5 + 0] = su[k];
            s[wid][k * 5 + 1] = su2[k];
            s[wid][k * 5 + 2] = sy[k];
            s[wid][k * 5 + 3] = sy2[k];
            s[wid][k * 5 + 4] = (float)cnt[k];
        }
    }
    __syncthreads();

    // Threads 0..7 finalize one row each (combine 4 warps, apply closed form).
    __shared__ float2 rowRes[8];
    if (tid < 8) {
        const int base = tid * 4;
        float tot = 0.f, count = 0.f;
        #pragma unroll
        for (int k = 0; k < 3; k++) {
            float Su = 0.f, Su2 = 0.f, Sy = 0.f, Sy2 = 0.f, m = 0.f;
            #pragma unroll
            for (int w = 0; w < 4; w++) {
                Su  += s[base + w][k * 5 + 0];
                Su2 += s[base + w][k * 5 + 1];
                Sy  += s[base + w][k * 5 + 2];
                Sy2 += s[base + w][k * 5 + 3];
                m   += s[base + w][k * 5 + 4];
            }
            tot   += (m - 2.f) * Su2 + Su * Su + m * Sy2 - Sy * Sy;
            count += 0.5f * m * (m - 1.f);
        }
        rowRes[tid] = make_float2(tot, count);
    }
    __syncthreads();

    if (tid == 0) {
        float tot = 0.f, count = 0.f;
        #pragma unroll
        for (int r = 0; r < 8; r++) { tot += rowRes[r].x; count += rowRes[r].y; }

        atomicAdd(&g_total, tot);    // return unused -> REDG
        atomicAdd(&g_count, count);  // return unused -> REDG
        __threadfence();
        const unsigned int done = atomicAdd(&g_done, 1u);
        if (done == gridDim.x - 1) {
            // Last block: all prior atomics visible (fenced above).
            const float t = *((volatile float*)&g_total);
            const float c = *((volatile float*)&g_count);
            out[0] = t / fmaxf(c, 1.f);
            // Self-reset so each graph replay starts clean (deterministic).
            *((volatile float*)&g_total) = 0.f;
            *((volatile float*)&g_count) = 0.f;
            __threadfence();
            *((volatile unsigned int*)&g_done) = 0u;
        }
    }
}

extern "C" void kernel_launch(void* const* d_in, const int* in_sizes, int n_in,
                              void* d_out, int out_size)
{
    const float* kp  = (const float*)d_in[0];   // [B, N, 2] float32
    const int*   cls = (const int*)d_in[1];     // [B, N] int32
    float* out = (float*)d_out;

    const int BN = in_sizes[1];   // B * N = 131072
    const int B  = BN / 512;      // 256
    sym_ballot_kernel<<<B / 8, 1024>>>(kp, cls, out);
}

// round 9
// speedup vs baseline: 1.2768x; 1.0295x over previous
#include <cuda_runtime.h>

// Closed-form symmetry constraint:
// Per (batch row, class c in {0,1,2}) group of size m with u = x - 0.5:
//   sum_{i<j} (u_i+u_j)^2 = (m-2)*Su2 + Su^2
//   sum_{i<j} (y_i-y_j)^2 = m*Sy2 - Sy^2
//   pairs = m*(m-1)/2
// Output = total / max(count, 1)
//
// 64 blocks x 512 threads (spread across 64 SMs -> 4 warps/SMSP; halves the
// per-SMSP instruction load vs 32x1024 while keeping enough warps to hide
// latency). Each block owns 4 rows (4 warps/row); each thread owns ONE int4
// chunk (4 keypoints): 3 independent 16B loads. Accumulation uses a float
// mask + FFMA (6 instrs per elem-class vs 9 for select+add). Counts via
// ballot+popc. 12-value butterfly, block finalize, 64-deep atomic tail.

__device__ float g_total;
__device__ float g_count;
__device__ unsigned int g_done;

__global__ void __launch_bounds__(512)
sym_spread_kernel(const float* __restrict__ kp,   // [B, N, 2]
                  const int*   __restrict__ cls,  // [B, N]
                  float* __restrict__ out)
{
    const int tid  = threadIdx.x;
    const int wid  = tid >> 5;          // 0..15
    const int lane = tid & 31;
    const int rowInBlk = wid >> 2;      // 0..3
    const int b        = blockIdx.x * 4 + rowInBlk;
    const int chunk    = ((wid & 3) << 5) | lane;     // 0..127
    const size_t gchunk = (size_t)b * 128 + chunk;

    // 3 independent wide loads, issued back-to-back.
    const int4   c4  = reinterpret_cast<const int4*>(cls)[gchunk];
    const float4 p01 = reinterpret_cast<const float4*>(kp)[gchunk * 2];
    const float4 p23 = reinterpret_cast<const float4*>(kp)[gchunk * 2 + 1];

    float su[3]  = {0.f, 0.f, 0.f};
    float su2[3] = {0.f, 0.f, 0.f};
    float sy[3]  = {0.f, 0.f, 0.f};
    float sy2[3] = {0.f, 0.f, 0.f};

    // Mask-FFMA accumulation (compile-time class indices only).
    {
        const int   cc[4] = {c4.x, c4.y, c4.z, c4.w};
        const float xs[4] = {p01.x, p01.z, p23.x, p23.z};
        const float ys[4] = {p01.y, p01.w, p23.y, p23.w};
        #pragma unroll
        for (int e = 0; e < 4; e++) {
            const float u  = xs[e] - 0.5f;
            const float uu = u * u;
            const float y  = ys[e];
            const float yy = y * y;
            #pragma unroll
            for (int k = 0; k < 3; k++) {
                const float mk = (cc[e] == k) ? 1.f : 0.f;
                su[k]  = fmaf(mk, u,  su[k]);
                su2[k] = fmaf(mk, uu, su2[k]);
                sy[k]  = fmaf(mk, y,  sy[k]);
                sy2[k] = fmaf(mk, yy, sy2[k]);
            }
        }
    }

    // Warp-uniform class counts via ballot+popc.
    int cnt[3];
    #pragma unroll
    for (int k = 0; k < 3; k++) {
        cnt[k] = __popc(__ballot_sync(0xFFFFFFFFu, c4.x == k))
               + __popc(__ballot_sync(0xFFFFFFFFu, c4.y == k))
               + __popc(__ballot_sync(0xFFFFFFFFu, c4.z == k))
               + __popc(__ballot_sync(0xFFFFFFFFu, c4.w == k));
    }

    // Butterfly-reduce the 12 float moments across the warp.
    #pragma unroll
    for (int off = 16; off > 0; off >>= 1) {
        #pragma unroll
        for (int k = 0; k < 3; k++) {
            su[k]  += __shfl_xor_sync(0xFFFFFFFFu, su[k],  off);
            su2[k] += __shfl_xor_sync(0xFFFFFFFFu, su2[k], off);
            sy[k]  += __shfl_xor_sync(0xFFFFFFFFu, sy[k],  off);
            sy2[k] += __shfl_xor_sync(0xFFFFFFFFu, sy2[k], off);
        }
    }

    // Per-warp partials: 12 floats + 3 counts (as float).
    __shared__ float s[16][16];
    if (lane == 0) {
        #pragma unroll
        for (int k = 0; k < 3; k++) {
            s[wid][k * 5 + 0] = su[k];
            s[wid][k * 5 + 1] = su2[k];
            s[wid][k * 5 + 2] = sy[k];
            s[wid][k * 5 + 3] = sy2[k];
            s[wid][k * 5 + 4] = (float)cnt[k];
        }
    }
    __syncthreads();

    // Threads 0..3 finalize one row each (combine 4 warps, closed form).
    __shared__ float2 rowRes[4];
    if (tid < 4) {
        const int base = tid * 4;
        float tot = 0.f, count = 0.f;
        #pragma unroll
        for (int k = 0; k < 3; k++) {
            float Su = 0.f, Su2 = 0.f, Sy = 0.f, Sy2 = 0.f, m = 0.f;
            #pragma unroll
            for (int w = 0; w < 4; w++) {
                Su  += s[base + w][k * 5 + 0];
                Su2 += s[base + w][k * 5 + 1];
                Sy  += s[base + w][k * 5 + 2];
                Sy2 += s[base + w][k * 5 + 3];
                m   += s[base + w][k * 5 + 4];
            }
            tot   += (m - 2.f) * Su2 + Su * Su + m * Sy2 - Sy * Sy;
            count += 0.5f * m * (m - 1.f);
        }
        rowRes[tid] = make_float2(tot, count);
    }
    __syncthreads();

    if (tid == 0) {
        float tot = 0.f, count = 0.f;
        #pragma unroll
        for (int r = 0; r < 4; r++) { tot += rowRes[r].x; count += rowRes[r].y; }

        atomicAdd(&g_total, tot);    // return unused -> REDG
        atomicAdd(&g_count, count);  // return unused -> REDG
        __threadfence();
        const unsigned int done = atomicAdd(&g_done, 1u);
        if (done == gridDim.x - 1) {
            // Last block: all prior atomics visible (fenced above).
            const float t = *((volatile float*)&g_total);
            const float c = *((volatile float*)&g_count);
            out[0] = t / fmaxf(c, 1.f);
            // Self-reset so each graph replay starts clean (deterministic).
            *((volatile float*)&g_total) = 0.f;
            *((volatile float*)&g_count) = 0.f;
            __threadfence();
            *((volatile unsigned int*)&g_done) = 0u;
        }
    }
}

extern "C" void kernel_launch(void* const* d_in, const int* in_sizes, int n_in,
                              void* d_out, int out_size)
{
    const float* kp  = (const float*)d_in[0];   // [B, N, 2] float32
    const int*   cls = (const int*)d_in[1];     // [B, N] int32
    float* out = (float*)d_out;

    const int BN = in_sizes[1];   // B * N = 131072
    const int B  = BN / 512;      // 256
    sym_spread_kernel<<<B / 4, 512>>>(kp, cls, out);
}